// round 3
// baseline (speedup 1.0000x reference)
#include <cuda_runtime.h>
#include <math.h>
#include <stdint.h>

#define NT   8192      // tokens
#define DIMK 4096      // hidden dim
#define NE   64        // experts
#define TOPK 8
#define RSCALE 2.5f

#define TM      64     // tokens per CTA
#define BK      16     // K-chunk (fp32 elems)
#define NTHR    128    // threads per CTA
#define NITER   (DIMK / BK)   // 256

// packed f32x2 ops (two independent fp32 lanes in one 64-bit reg)
__device__ __forceinline__ void ffma2(unsigned long long &d,
                                      unsigned long long a,
                                      unsigned long long b) {
    asm("fma.rn.f32x2 %0, %1, %2, %0;" : "+l"(d) : "l"(a), "l"(b));
}
__device__ __forceinline__ void fmul2(unsigned long long &d,
                                      unsigned long long a,
                                      unsigned long long b) {
    asm("mul.rn.f32x2 %0, %1, %2;" : "=l"(d) : "l"(a), "l"(b));
}
__device__ __forceinline__ void fadd2(unsigned long long &d,
                                      unsigned long long a) {
    asm("add.rn.f32x2 %0, %0, %1;" : "+l"(d) : "l"(a));
}

__global__ void zero_hist_kernel(float* __restrict__ out) {
    out[2 * NT * TOPK + threadIdx.x] = 0.0f;
}

__global__ __launch_bounds__(NTHR)
void router_kernel(const float* __restrict__ x,
                   const float* __restrict__ w,
                   const float* __restrict__ bias,
                   float* __restrict__ out) {
    // xs: transposed x tile [k][token]; ws: duplicated W tile [k][2*expert]
    __shared__ float xs[2][BK][68];
    __shared__ float ws[2][BK][130];
    __shared__ float logits[TM][65];
    __shared__ int   shist[NE];

    const int tid = threadIdx.x;
    const int tx  = tid & 15;        // expert group: experts tx + 16*j
    const int ty  = tid >> 4;        // token group: tokens ty*8 .. ty*8+7
    const int t0  = ty * 8;
    const int blockRow = blockIdx.x * TM;

    if (tid < NE) shist[tid] = 0;

    float4 xr[2], wr[2];

    #define LOAD_TILE(IT) do {                                                   \
        const int kb = (IT) * BK;                                                \
        _Pragma("unroll")                                                        \
        for (int i = 0; i < 2; i++) {                                            \
            const int f = tid + 128 * i;                                         \
            const int r = f >> 2, c = f & 3;                                     \
            xr[i] = *reinterpret_cast<const float4*>(                            \
                &x[(size_t)(blockRow + r) * DIMK + kb + c * 4]);                 \
            wr[i] = *reinterpret_cast<const float4*>(                            \
                &w[(size_t)r * DIMK + kb + c * 4]);                              \
        }                                                                        \
    } while (0)

    #define STORE_TILE(B) do {                                                   \
        _Pragma("unroll")                                                        \
        for (int i = 0; i < 2; i++) {                                            \
            const int f = tid + 128 * i;                                         \
            const int r = f >> 2, c = f & 3;                                     \
            xs[B][c * 4 + 0][r] = xr[i].x;                                       \
            xs[B][c * 4 + 1][r] = xr[i].y;                                       \
            xs[B][c * 4 + 2][r] = xr[i].z;                                       \
            xs[B][c * 4 + 3][r] = xr[i].w;                                       \
            ws[B][c * 4 + 0][2 * r] = wr[i].x; ws[B][c * 4 + 0][2 * r + 1] = wr[i].x; \
            ws[B][c * 4 + 1][2 * r] = wr[i].y; ws[B][c * 4 + 1][2 * r + 1] = wr[i].y; \
            ws[B][c * 4 + 2][2 * r] = wr[i].z; ws[B][c * 4 + 2][2 * r + 1] = wr[i].z; \
            ws[B][c * 4 + 3][2 * r] = wr[i].w; ws[B][c * 4 + 3][2 * r + 1] = wr[i].w; \
        }                                                                        \
    } while (0)

    // 3-level cascaded accumulators (packed token-pair x expert):
    //   accT: 16-term tile chain (seeded by mul, no zeroing)
    //   accM: sums 16 tiles, then drains into accF and resets
    //   accF: sums 16 group partials (final logits)
    unsigned long long accT[4][4], accM[4][4], accF[4][4];
    #pragma unroll
    for (int p = 0; p < 4; p++)
        #pragma unroll
        for (int j = 0; j < 4; j++) { accM[p][j] = 0ULL; accF[p][j] = 0ULL; }

    LOAD_TILE(0);
    STORE_TILE(0);
    __syncthreads();

    for (int it = 0; it < NITER; ++it) {
        const int b = it & 1;
        if (it + 1 < NITER) LOAD_TILE(it + 1);

        #pragma unroll
        for (int kk = 0; kk < BK; kk++) {
            const ulonglong2 A0 =
                *reinterpret_cast<const ulonglong2*>(&xs[b][kk][t0]);
            const ulonglong2 A1 =
                *reinterpret_cast<const ulonglong2*>(&xs[b][kk][t0 + 4]);
            unsigned long long Bv[4];
            #pragma unroll
            for (int j = 0; j < 4; j++)
                Bv[j] = *reinterpret_cast<const unsigned long long*>(
                    &ws[b][kk][2 * (tx + 16 * j)]);
            if (kk == 0) {
                #pragma unroll
                for (int j = 0; j < 4; j++) {
                    fmul2(accT[0][j], A0.x, Bv[j]);
                    fmul2(accT[1][j], A0.y, Bv[j]);
                    fmul2(accT[2][j], A1.x, Bv[j]);
                    fmul2(accT[3][j], A1.y, Bv[j]);
                }
            } else {
                #pragma unroll
                for (int j = 0; j < 4; j++) {
                    ffma2(accT[0][j], A0.x, Bv[j]);
                    ffma2(accT[1][j], A0.y, Bv[j]);
                    ffma2(accT[2][j], A1.x, Bv[j]);
                    ffma2(accT[3][j], A1.y, Bv[j]);
                }
            }
        }

        // mid-level: accM += tile partial
        #pragma unroll
        for (int p = 0; p < 4; p++)
            #pragma unroll
            for (int j = 0; j < 4; j++) fadd2(accM[p][j], accT[p][j]);

        // every 16 tiles: drain group partial into final accumulator
        if ((it & 15) == 15) {
            #pragma unroll
            for (int p = 0; p < 4; p++)
                #pragma unroll
                for (int j = 0; j < 4; j++) {
                    fadd2(accF[p][j], accM[p][j]);
                    accM[p][j] = 0ULL;
                }
        }

        if (it + 1 < NITER) {
            STORE_TILE((it + 1) & 1);
            __syncthreads();
        }
    }

    // ---- epilogue: scatter final logits to smem ----
    #pragma unroll
    for (int p = 0; p < 4; p++) {
        #pragma unroll
        for (int j = 0; j < 4; j++) {
            const unsigned long long u = accF[p][j];
            const float lo = __uint_as_float((unsigned)(u & 0xffffffffu));
            const float hi = __uint_as_float((unsigned)(u >> 32));
            const int e = tx + 16 * j;
            logits[t0 + 2 * p][e]     = lo;
            logits[t0 + 2 * p + 1][e] = hi;
        }
    }
    __syncthreads();

    // ---- routing: 4 warps x 16 tokens each ----
    const int lane = tid & 31;
    const int wrp  = tid >> 5;
    const float bias0 = bias[lane];
    const float bias1 = bias[lane + 32];

    for (int tt = wrp * 16; tt < wrp * 16 + 16; tt++) {
        const float l0 = logits[tt][lane];
        const float l1 = logits[tt][lane + 32];
        const float s0 = 1.0f / (1.0f + expf(-l0));
        const float s1 = 1.0f / (1.0f + expf(-l1));
        float b0 = s0 + bias0;
        float b1 = s1 + bias1;

        float denom = 0.0f;
        float selVal = 0.0f;
        int   selIdx = 0;

        #pragma unroll
        for (int k = 0; k < TOPK; k++) {
            // local candidate: lowest-index tie-break (prefer lane over lane+32)
            float v = b0; int ix = lane;
            if (b1 > v) { v = b1; ix = lane + 32; }
            // warp argmax, lowest-index on ties
            #pragma unroll
            for (int off = 16; off > 0; off >>= 1) {
                const float ov = __shfl_xor_sync(0xffffffffu, v, off);
                const int   oi = __shfl_xor_sync(0xffffffffu, ix, off);
                if (ov > v || (ov == v && oi < ix)) { v = ov; ix = oi; }
            }
            // gather UNBIASED score at winner
            const float g0 = __shfl_sync(0xffffffffu, s0, ix & 31);
            const float g1 = __shfl_sync(0xffffffffu, s1, ix & 31);
            const float sv = (ix < 32) ? g0 : g1;
            denom += sv;
            if (lane == k) { selVal = sv; selIdx = ix; }
            if (lane == (ix & 31)) {
                if (ix < 32) b0 = -INFINITY; else b1 = -INFINITY;
            }
            if (lane == 0) atomicAdd(&shist[ix], 1);
        }

        const float scale = RSCALE / (denom + 1e-20f);
        const int tg = blockRow + tt;
        if (lane < TOPK) {
            out[tg * TOPK + lane]             = selVal * scale;
            out[NT * TOPK + tg * TOPK + lane] = (float)selIdx;
        }
    }

    __syncthreads();
    if (tid < NE) atomicAdd(&out[2 * NT * TOPK + tid], (float)shist[tid]);
}

extern "C" void kernel_launch(void* const* d_in, const int* in_sizes, int n_in,
                              void* d_out, int out_size) {
    const float* x    = (const float*)d_in[0];   // [8192, 4096] f32
    const float* w    = (const float*)d_in[1];   // [64, 4096]   f32
    const float* bias = (const float*)d_in[2];   // [64]         f32
    float* out = (float*)d_out;                  // [N*K scores | N*K idx | 64 hist]

    zero_hist_kernel<<<1, NE>>>(out);
    router_kernel<<<NT / TM, NTHR>>>(x, w, bias, out);
}

// round 4
// speedup vs baseline: 1.0005x; 1.0005x over previous
#include <cuda_runtime.h>
#include <math.h>
#include <stdint.h>

#define NT   8192      // tokens
#define DIMK 4096      // hidden dim
#define NE   64        // experts
#define TOPK 8
#define RSCALE 2.5f

#define TM      64     // tokens per CTA
#define BK      16     // K-chunk (fp32 elems)
#define NTHR    128    // threads per CTA
#define NITER   (DIMK / BK)   // 256

// packed f32x2 ops (two independent fp32 lanes in one 64-bit reg)
__device__ __forceinline__ void ffma2(unsigned long long &d,
                                      unsigned long long a,
                                      unsigned long long b) {
    asm("fma.rn.f32x2 %0, %1, %2, %0;" : "+l"(d) : "l"(a), "l"(b));
}
__device__ __forceinline__ void fmul2(unsigned long long &d,
                                      unsigned long long a,
                                      unsigned long long b) {
    asm("mul.rn.f32x2 %0, %1, %2;" : "=l"(d) : "l"(a), "l"(b));
}
__device__ __forceinline__ void fadd2(unsigned long long &d,
                                      unsigned long long a) {
    asm("add.rn.f32x2 %0, %0, %1;" : "+l"(d) : "l"(a));
}

__global__ void zero_hist_kernel(float* __restrict__ out) {
    out[2 * NT * TOPK + threadIdx.x] = 0.0f;
}

__global__ __launch_bounds__(NTHR)
void router_kernel(const float* __restrict__ x,
                   const float* __restrict__ w,
                   const float* __restrict__ bias,
                   float* __restrict__ out) {
    // xs: transposed x tile [k][token]; ws: duplicated W tile [k][2*expert]
    __shared__ float xs[2][BK][68];
    __shared__ float ws[2][BK][130];
    __shared__ float logits[TM][65];
    __shared__ int   shist[NE];

    const int tid = threadIdx.x;
    const int tx  = tid & 15;        // expert group: experts tx + 16*j
    const int ty  = tid >> 4;        // token group: tokens ty*8 .. ty*8+7
    const int t0  = ty * 8;
    const int blockRow = blockIdx.x * TM;

    if (tid < NE) shist[tid] = 0;

    float4 xr[2], wr[2];

    #define LOAD_TILE(IT) do {                                                   \
        const int kb = (IT) * BK;                                                \
        _Pragma("unroll")                                                        \
        for (int i = 0; i < 2; i++) {                                            \
            const int f = tid + 128 * i;                                         \
            const int r = f >> 2, c = f & 3;                                     \
            xr[i] = *reinterpret_cast<const float4*>(                            \
                &x[(size_t)(blockRow + r) * DIMK + kb + c * 4]);                 \
            wr[i] = *reinterpret_cast<const float4*>(                            \
                &w[(size_t)r * DIMK + kb + c * 4]);                              \
        }                                                                        \
    } while (0)

    #define STORE_TILE(B) do {                                                   \
        _Pragma("unroll")                                                        \
        for (int i = 0; i < 2; i++) {                                            \
            const int f = tid + 128 * i;                                         \
            const int r = f >> 2, c = f & 3;                                     \
            xs[B][c * 4 + 0][r] = xr[i].x;                                       \
            xs[B][c * 4 + 1][r] = xr[i].y;                                       \
            xs[B][c * 4 + 2][r] = xr[i].z;                                       \
            xs[B][c * 4 + 3][r] = xr[i].w;                                       \
            ws[B][c * 4 + 0][2 * r] = wr[i].x; ws[B][c * 4 + 0][2 * r + 1] = wr[i].x; \
            ws[B][c * 4 + 1][2 * r] = wr[i].y; ws[B][c * 4 + 1][2 * r + 1] = wr[i].y; \
            ws[B][c * 4 + 2][2 * r] = wr[i].z; ws[B][c * 4 + 2][2 * r + 1] = wr[i].z; \
            ws[B][c * 4 + 3][2 * r] = wr[i].w; ws[B][c * 4 + 3][2 * r + 1] = wr[i].w; \
        }                                                                        \
    } while (0)

    // 3-level cascaded accumulators (packed token-pair x expert):
    //   accT: 16-term tile chain (seeded by mul, no zeroing)
    //   accM: sums 16 tiles, then drains into accF and resets
    //   accF: sums 16 group partials (final logits)
    unsigned long long accT[4][4], accM[4][4], accF[4][4];
    #pragma unroll
    for (int p = 0; p < 4; p++)
        #pragma unroll
        for (int j = 0; j < 4; j++) { accM[p][j] = 0ULL; accF[p][j] = 0ULL; }

    LOAD_TILE(0);
    STORE_TILE(0);
    __syncthreads();

    for (int it = 0; it < NITER; ++it) {
        const int b = it & 1;
        if (it + 1 < NITER) LOAD_TILE(it + 1);

        #pragma unroll
        for (int kk = 0; kk < BK; kk++) {
            const ulonglong2 A0 =
                *reinterpret_cast<const ulonglong2*>(&xs[b][kk][t0]);
            const ulonglong2 A1 =
                *reinterpret_cast<const ulonglong2*>(&xs[b][kk][t0 + 4]);
            unsigned long long Bv[4];
            #pragma unroll
            for (int j = 0; j < 4; j++)
                Bv[j] = *reinterpret_cast<const unsigned long long*>(
                    &ws[b][kk][2 * (tx + 16 * j)]);
            if (kk == 0) {
                #pragma unroll
                for (int j = 0; j < 4; j++) {
                    fmul2(accT[0][j], A0.x, Bv[j]);
                    fmul2(accT[1][j], A0.y, Bv[j]);
                    fmul2(accT[2][j], A1.x, Bv[j]);
                    fmul2(accT[3][j], A1.y, Bv[j]);
                }
            } else {
                #pragma unroll
                for (int j = 0; j < 4; j++) {
                    ffma2(accT[0][j], A0.x, Bv[j]);
                    ffma2(accT[1][j], A0.y, Bv[j]);
                    ffma2(accT[2][j], A1.x, Bv[j]);
                    ffma2(accT[3][j], A1.y, Bv[j]);
                }
            }
        }

        // mid-level: accM += tile partial
        #pragma unroll
        for (int p = 0; p < 4; p++)
            #pragma unroll
            for (int j = 0; j < 4; j++) fadd2(accM[p][j], accT[p][j]);

        // every 16 tiles: drain group partial into final accumulator
        if ((it & 15) == 15) {
            #pragma unroll
            for (int p = 0; p < 4; p++)
                #pragma unroll
                for (int j = 0; j < 4; j++) {
                    fadd2(accF[p][j], accM[p][j]);
                    accM[p][j] = 0ULL;
                }
        }

        if (it + 1 < NITER) {
            STORE_TILE((it + 1) & 1);
            __syncthreads();
        }
    }

    // ---- epilogue: scatter final logits to smem ----
    #pragma unroll
    for (int p = 0; p < 4; p++) {
        #pragma unroll
        for (int j = 0; j < 4; j++) {
            const unsigned long long u = accF[p][j];
            const float lo = __uint_as_float((unsigned)(u & 0xffffffffu));
            const float hi = __uint_as_float((unsigned)(u >> 32));
            const int e = tx + 16 * j;
            logits[t0 + 2 * p][e]     = lo;
            logits[t0 + 2 * p + 1][e] = hi;
        }
    }
    __syncthreads();

    // ---- routing: 4 warps x 16 tokens each ----
    const int lane = tid & 31;
    const int wrp  = tid >> 5;
    const float bias0 = bias[lane];
    const float bias1 = bias[lane + 32];

    for (int tt = wrp * 16; tt < wrp * 16 + 16; tt++) {
        const float l0 = logits[tt][lane];
        const float l1 = logits[tt][lane + 32];
        const float s0 = 1.0f / (1.0f + expf(-l0));
        const float s1 = 1.0f / (1.0f + expf(-l1));
        float b0 = s0 + bias0;
        float b1 = s1 + bias1;

        float denom = 0.0f;
        float selVal = 0.0f;
        int   selIdx = 0;

        #pragma unroll
        for (int k = 0; k < TOPK; k++) {
            // local candidate: lowest-index tie-break (prefer lane over lane+32)
            float v = b0; int ix = lane;
            if (b1 > v) { v = b1; ix = lane + 32; }
            // warp argmax, lowest-index on ties
            #pragma unroll
            for (int off = 16; off > 0; off >>= 1) {
                const float ov = __shfl_xor_sync(0xffffffffu, v, off);
                const int   oi = __shfl_xor_sync(0xffffffffu, ix, off);
                if (ov > v || (ov == v && oi < ix)) { v = ov; ix = oi; }
            }
            // gather UNBIASED score at winner
            const float g0 = __shfl_sync(0xffffffffu, s0, ix & 31);
            const float g1 = __shfl_sync(0xffffffffu, s1, ix & 31);
            const float sv = (ix < 32) ? g0 : g1;
            denom += sv;
            if (lane == k) { selVal = sv; selIdx = ix; }
            if (lane == (ix & 31)) {
                if (ix < 32) b0 = -INFINITY; else b1 = -INFINITY;
            }
            if (lane == 0) atomicAdd(&shist[ix], 1);
        }

        const float scale = RSCALE / (denom + 1e-20f);
        const int tg = blockRow + tt;
        if (lane < TOPK) {
            out[tg * TOPK + lane]             = selVal * scale;
            out[NT * TOPK + tg * TOPK + lane] = (float)selIdx;
        }
    }

    __syncthreads();
    if (tid < NE) atomicAdd(&out[2 * NT * TOPK + tid], (float)shist[tid]);
}

extern "C" void kernel_launch(void* const* d_in, const int* in_sizes, int n_in,
                              void* d_out, int out_size) {
    const float* x    = (const float*)d_in[0];   // [8192, 4096] f32
    const float* w    = (const float*)d_in[1];   // [64, 4096]   f32
    const float* bias = (const float*)d_in[2];   // [64]         f32
    float* out = (float*)d_out;                  // [N*K scores | N*K idx | 64 hist]

    zero_hist_kernel<<<1, NE>>>(out);
    router_kernel<<<NT / TM, NTHR>>>(x, w, bias, out);
}

// round 8
// speedup vs baseline: 1.6731x; 1.6723x over previous
#include <cuda_runtime.h>
#include <cuda_fp16.h>
#include <math.h>
#include <stdint.h>

#define NT 8192
#define DIMK 4096
#define NE 64
#define TOPK 8
#define RSCALE 2.5f
#define NCHUNK 64
#define NCTA 128
#define NTHR 256
#define SM_A 0          // A tiles: 2 bufs x 3 terms x 8192
#define SM_W 49152      // W frags: 2 bufs x 3 terms x 8192
#define DSMEM 98304
#define INV2048 4.8828125e-4f
#define INV2048SQ 2.384185791015625e-7f

__device__ uint2 w_img[NCHUNK * 3072];  // 1.5MB frag-layout 3-way W split

__device__ __forceinline__ uint32_t swz(uint32_t x) { return x ^ ((x >> 3) & 0x70u); }
__device__ __forceinline__ uint32_t smem_u32(const void* p) {
    uint32_t a;
    asm("{ .reg .u64 t; cvta.to.shared.u64 t, %1; cvt.u32.u64 %0, t; }" : "=r"(a) : "l"(p));
    return a;
}
#define LDM(R, a) asm volatile( \
    "ldmatrix.sync.aligned.m8n8.x4.shared.b16 {%0,%1,%2,%3}, [%4];" \
    : "=r"((R)[0]), "=r"((R)[1]), "=r"((R)[2]), "=r"((R)[3]) : "r"(a))
#define MMA(C, A, B0, B1) asm volatile( \
    "mma.sync.aligned.m16n8k16.row.col.f32.f16.f16.f32 " \
    "{%0,%1,%2,%3},{%4,%5,%6,%7},{%8,%9},{%0,%1,%2,%3};" \
    : "+f"((C)[0]), "+f"((C)[1]), "+f"((C)[2]), "+f"((C)[3]) \
    : "r"((A)[0]), "r"((A)[1]), "r"((A)[2]), "r"((A)[3]), "r"(B0), "r"(B1))
#define LDS64(r0, r1, a) asm volatile("ld.shared.v2.u32 {%0,%1}, [%2];" \
    : "=r"(r0), "=r"(r1) : "r"(a))
#define CPA(d, s) asm volatile("cp.async.cg.shared.global [%0], [%1], 16;" :: "r"(d), "l"(s))
#define CPC() asm volatile("cp.async.commit_group;" ::: "memory")
#define CPW0() asm volatile("cp.async.wait_group 0;" ::: "memory")

__global__ void zero_hist_kernel(float* __restrict__ out) {
    out[2 * NT * TOPK + threadIdx.x] = 0.0f;
}

// exact 3-way fp16 split of one fp32: v = a + b/2048 + c/2048^2 (+ O(2^-33))
__device__ __forceinline__ void split3(float v, __half& a, __half& b, __half& c) {
    a = __float2half_rn(v);
    float r1 = v - __half2float(a);
    b = __float2half_rn(r1 * 2048.0f);
    float r2 = r1 - __half2float(b) * INV2048;
    c = __float2half_rn(r2 * 4194304.0f);
}

// W split into B-fragment-order image: chunk-major, term t in {a,b,c}
__global__ void wprep_kernel(const float* __restrict__ w) {
    int idx = blockIdx.x * blockDim.x + threadIdx.x;
    if (idx >= NCHUNK * 3072) return;
    int c = idx / 3072, rem = idx % 3072;
    int t = rem >> 10;                 // 0..2
    int rem2 = rem & 1023;
    int s = (rem2 >> 8) & 3, j = (rem2 >> 5) & 7, lane = rem2 & 31;
    int e = j * 8 + (lane >> 2);
    int k0 = c * 64 + s * 16 + (lane & 3) * 2;
    __half h[4];
    #pragma unroll
    for (int i = 0; i < 4; i++) {
        int k = k0 + (i >> 1) * 8 + (i & 1);
        __half ha, hb, hc;
        split3(w[e * DIMK + k], ha, hb, hc);
        h[i] = (t == 0) ? ha : (t == 1 ? hb : hc);
    }
    uint2 o;
    o.x = (uint32_t)__half_as_ushort(h[0]) | ((uint32_t)__half_as_ushort(h[1]) << 16);
    o.y = (uint32_t)__half_as_ushort(h[2]) | ((uint32_t)__half_as_ushort(h[3]) << 16);
    w_img[idx] = o;
}

__global__ void __launch_bounds__(NTHR)
router_kernel(const float* __restrict__ x, const float* __restrict__ bias,
              float* __restrict__ out) {
    extern __shared__ char smem[];
    __shared__ int shist[NE];
    const uint32_t sb = smem_u32(smem);
    const int tid = threadIdx.x, wid = tid >> 5, lane = tid & 31;
    const int blockRow = blockIdx.x * 64;
    const int pr = tid >> 2, pq = tid & 3;
    const int mb = (wid & 3) * 16, nh = wid >> 2;

    if (tid < NE) shist[tid] = 0;

    float Cs[4][4], Cf1[4][4], Cf2[4][4], C2[4][4], C3[4][4];
    #pragma unroll
    for (int j = 0; j < 4; j++)
        #pragma unroll
        for (int v = 0; v < 4; v++) {
            Cs[j][v] = 0; Cf1[j][v] = 0; Cf2[j][v] = 0; C2[j][v] = 0; C3[j][v] = 0;
        }

    // preload W chunk0 (96B per thread) + x chunk0
    {
        const char* src = (const char*)w_img + (size_t)tid * 96;
        uint32_t dst = sb + SM_W + tid * 96;
        #pragma unroll
        for (int q = 0; q < 6; q++) CPA(dst + q * 16, src + q * 16);
        CPC();
    }
    float4 xc[4], xn[4];
    #pragma unroll
    for (int i = 0; i < 4; i++)
        xc[i] = *reinterpret_cast<const float4*>(
            &x[(size_t)(blockRow + pr) * DIMK + pq * 16 + i * 4]);

    const uint32_t lrow = (lane & 7) + ((lane >> 3) & 1) * 8;
    const uint32_t lcol16 = ((lane >> 4) & 1) * 16;

    for (int it = 0; it < NCHUNK; ++it) {
        const int b = it & 1;
        if (it + 1 < NCHUNK) {
            const int kb = (it + 1) * 64;
            #pragma unroll
            for (int i = 0; i < 4; i++)
                xn[i] = *reinterpret_cast<const float4*>(
                    &x[(size_t)(blockRow + pr) * DIMK + kb + pq * 16 + i * 4]);
        }
        // convert + store 3 A tiles (swizzled)
        {
            uint32_t aw[8], bw[8], cw[8];
            #pragma unroll
            for (int i = 0; i < 4; i++) {
                const float vv[4] = {xc[i].x, xc[i].y, xc[i].z, xc[i].w};
                #pragma unroll
                for (int p = 0; p < 2; p++) {
                    __half a0, b0, c0, a1, b1, c1;
                    split3(vv[p * 2], a0, b0, c0);
                    split3(vv[p * 2 + 1], a1, b1, c1);
                    aw[i * 2 + p] = (uint32_t)__half_as_ushort(a0) |
                                    ((uint32_t)__half_as_ushort(a1) << 16);
                    bw[i * 2 + p] = (uint32_t)__half_as_ushort(b0) |
                                    ((uint32_t)__half_as_ushort(b1) << 16);
                    cw[i * 2 + p] = (uint32_t)__half_as_ushort(c0) |
                                    ((uint32_t)__half_as_ushort(c1) << 16);
                }
            }
            uint32_t off = pr * 128 + pq * 32;
            char* A = smem + SM_A + b * 24576;
            *(uint4*)(A + swz(off))              = make_uint4(aw[0], aw[1], aw[2], aw[3]);
            *(uint4*)(A + swz(off + 16))         = make_uint4(aw[4], aw[5], aw[6], aw[7]);
            *(uint4*)(A + 8192 + swz(off))       = make_uint4(bw[0], bw[1], bw[2], bw[3]);
            *(uint4*)(A + 8192 + swz(off + 16))  = make_uint4(bw[4], bw[5], bw[6], bw[7]);
            *(uint4*)(A + 16384 + swz(off))      = make_uint4(cw[0], cw[1], cw[2], cw[3]);
            *(uint4*)(A + 16384 + swz(off + 16)) = make_uint4(cw[4], cw[5], cw[6], cw[7]);
        }
        CPW0();
        __syncthreads();
        if (it + 1 < NCHUNK) {
            const char* src = (const char*)w_img + (size_t)(it + 1) * 24576 + tid * 96;
            uint32_t dst = sb + SM_W + (b ^ 1) * 24576 + tid * 96;
            #pragma unroll
            for (int q = 0; q < 6; q++) CPA(dst + q * 16, src + q * 16);
            CPC();
        }
        {
            const uint32_t Abase = sb + SM_A + b * 24576;
            const uint32_t Wbase = sb + SM_W + b * 24576;
            #pragma unroll
            for (int s = 0; s < 4; s++) {
                uint32_t fa[4], fb[4], fc[4];
                uint32_t aoff = swz((mb + lrow) * 128 + s * 32 + lcol16);
                LDM(fa, Abase + aoff);
                LDM(fb, Abase + 8192 + aoff);
                LDM(fc, Abase + 16384 + aoff);
                #pragma unroll
                for (int jl = 0; jl < 4; jl++) {
                    uint32_t wi = ((s * 8 + nh * 4 + jl) * 32 + lane) * 8;
                    uint32_t wa0, wa1, wb0, wb1, wc0, wc1;
                    LDS64(wa0, wa1, Wbase + wi);
                    LDS64(wb0, wb1, Wbase + 8192 + wi);
                    LDS64(wc0, wc1, Wbase + 16384 + wi);
                    MMA(Cs[jl], fa, wa0, wa1);
                    MMA(C2[jl], fa, wb0, wb1);
                    MMA(C2[jl], fb, wa0, wa1);
                    MMA(C3[jl], fb, wb0, wb1);
                    MMA(C3[jl], fa, wc0, wc1);
                    MMA(C3[jl], fc, wa0, wa1);
                }
            }
        }
        if (it & 1) {
            #pragma unroll
            for (int j = 0; j < 4; j++)
                #pragma unroll
                for (int v = 0; v < 4; v++) { Cf1[j][v] += Cs[j][v]; Cs[j][v] = 0; }
        }
        if ((it & 7) == 7) {
            #pragma unroll
            for (int j = 0; j < 4; j++)
                #pragma unroll
                for (int v = 0; v < 4; v++) { Cf2[j][v] += Cf1[j][v]; Cf1[j][v] = 0; }
        }
        #pragma unroll
        for (int i = 0; i < 4; i++) xc[i] = xn[i];
    }

    // logits into smem (reuse W buf0 region)
    float* logits = reinterpret_cast<float*>(smem + SM_W);  // [64][65]
    #pragma unroll
    for (int jl = 0; jl < 4; jl++) {
        const int r0 = mb + (lane >> 2);
        const int c0 = nh * 32 + jl * 8 + (lane & 3) * 2;
        #pragma unroll
        for (int v = 0; v < 4; v++) {
            const int rr = r0 + (v >> 1) * 8, cc = c0 + (v & 1);
            logits[rr * 65 + cc] =
                Cf2[jl][v] + C2[jl][v] * INV2048 + C3[jl][v] * INV2048SQ;
        }
    }
    __syncthreads();

    const float bias0 = bias[lane];
    const float bias1 = bias[lane + 32];
    for (int tt = wid * 8; tt < wid * 8 + 8; tt++) {
        const float l0 = logits[tt * 65 + lane];
        const float l1 = logits[tt * 65 + lane + 32];
        const float s0 = 1.0f / (1.0f + expf(-l0));
        const float s1 = 1.0f / (1.0f + expf(-l1));
        float b0 = s0 + bias0, b1 = s1 + bias1;
        float denom = 0.0f, selVal = 0.0f;
        int selIdx = 0;
        #pragma unroll
        for (int k = 0; k < TOPK; k++) {
            float v = b0; int ix = lane;
            if (b1 > v) { v = b1; ix = lane + 32; }
            #pragma unroll
            for (int off = 16; off > 0; off >>= 1) {
                const float ov = __shfl_xor_sync(0xffffffffu, v, off);
                const int   oi = __shfl_xor_sync(0xffffffffu, ix, off);
                if (ov > v || (ov == v && oi < ix)) { v = ov; ix = oi; }
            }
            const float g0 = __shfl_sync(0xffffffffu, s0, ix & 31);
            const float g1 = __shfl_sync(0xffffffffu, s1, ix & 31);
            const float sv = (ix < 32) ? g0 : g1;
            denom += sv;
            if (lane == k) { selVal = sv; selIdx = ix; }
            if (lane == (ix & 31)) { if (ix < 32) b0 = -INFINITY; else b1 = -INFINITY; }
            if (lane == 0) atomicAdd(&shist[ix], 1);
        }
        const float scale = RSCALE / (denom + 1e-20f);
        const int tg = blockRow + tt;
        if (lane < TOPK) {
            out[tg * TOPK + lane]             = selVal * scale;
            out[NT * TOPK + tg * TOPK + lane] = (float)selIdx;
        }
    }
    __syncthreads();
    if (tid < NE) atomicAdd(&out[2 * NT * TOPK + tid], (float)shist[tid]);
}

extern "C" void kernel_launch(void* const* d_in, const int* in_sizes, int n_in,
                              void* d_out, int out_size) {
    const float* x    = (const float*)d_in[0];
    const float* w    = (const float*)d_in[1];
    const float* bias = (const float*)d_in[2];
    float* out = (float*)d_out;

    cudaFuncSetAttribute(router_kernel,
                         cudaFuncAttributeMaxDynamicSharedMemorySize, DSMEM);
    zero_hist_kernel<<<1, NE>>>(out);
    wprep_kernel<<<(NCHUNK * 3072 + 255) / 256, 256>>>(w);
    router_kernel<<<NCTA, NTHR, DSMEM>>>(x, bias, out);
}